// round 1
// baseline (speedup 1.0000x reference)
#include <cuda_runtime.h>
#include <math.h>

#define H    3072
#define NH   24
#define HD   128
#define MLPD 12288
#define LT   512
#define LI   1024
#define L    1536
#define QKV3 9216
#define MOD6 18432

// ---------------- scratch (device globals; no allocations) ----------------
__device__ float g_mod_img[MOD6];
__device__ float g_mod_txt[MOD6];
__device__ float g_xmod[(size_t)L * H];
__device__ float g_qkv [(size_t)L * QKV3];
__device__ float g_q   [(size_t)NH * L * HD];
__device__ float g_k   [(size_t)NH * L * HD];
__device__ float g_v   [(size_t)NH * L * HD];
__device__ float g_S   [(size_t)NH * L * L];
__device__ float g_attn[(size_t)L * H];
__device__ float g_res2[(size_t)L * H];
__device__ float g_hbuf[(size_t)L * H];
__device__ float g_fc1 [(size_t)L * MLPD];

// ---------------- helpers ----------------
__device__ __forceinline__ float block_reduce_sum(float v, float* sh) {
    #pragma unroll
    for (int o = 16; o; o >>= 1) v += __shfl_xor_sync(0xffffffffu, v, o);
    int w = threadIdx.x >> 5;
    if ((threadIdx.x & 31) == 0) sh[w] = v;
    __syncthreads();
    if (threadIdx.x < 32) {
        float x = (threadIdx.x < (blockDim.x >> 5)) ? sh[threadIdx.x] : 0.f;
        #pragma unroll
        for (int o = 16; o; o >>= 1) x += __shfl_xor_sync(0xffffffffu, x, o);
        if (threadIdx.x == 0) sh[0] = x;
    }
    __syncthreads();
    return sh[0];
}

__device__ __forceinline__ float block_reduce_max(float v, float* sh) {
    #pragma unroll
    for (int o = 16; o; o >>= 1) v = fmaxf(v, __shfl_xor_sync(0xffffffffu, v, o));
    int w = threadIdx.x >> 5;
    if ((threadIdx.x & 31) == 0) sh[w] = v;
    __syncthreads();
    if (threadIdx.x < 32) {
        float x = (threadIdx.x < (blockDim.x >> 5)) ? sh[threadIdx.x] : -3.4e38f;
        #pragma unroll
        for (int o = 16; o; o >>= 1) x = fmaxf(x, __shfl_xor_sync(0xffffffffu, x, o));
        if (threadIdx.x == 0) sh[0] = x;
    }
    __syncthreads();
    return sh[0];
}

// ---------------- 1) modulation GEMV: out[j] = sum_i silu(vec[i]) * w[i,j] + b[j] ----------------
__global__ void __launch_bounds__(256) mod_gemv(const float* __restrict__ vec,
                                                const float* __restrict__ w,
                                                const float* __restrict__ b,
                                                float* __restrict__ out) {
    __shared__ float sv[H];
    for (int i = threadIdx.x; i < H; i += 256) {
        float x = vec[i];
        sv[i] = x / (1.f + expf(-x));
    }
    __syncthreads();
    int col = blockIdx.x * 256 + threadIdx.x;
    float acc = b[col];
    const float* wp = w + col;
    #pragma unroll 8
    for (int i = 0; i < H; i++) acc += sv[i] * wp[(size_t)i * MOD6];
    out[col] = acc;
}

// ---------------- 2) LayerNorm + modulate ----------------
__global__ void __launch_bounds__(256) ln_mod_kernel(const float* __restrict__ x,
                                                     float* __restrict__ y,
                                                     const float* __restrict__ sh,
                                                     const float* __restrict__ sc) {
    __shared__ float s0[32], s1[32];
    int row = blockIdx.x;
    const float* xr = x + (size_t)row * H;
    float s = 0.f, s2 = 0.f;
    for (int j = threadIdx.x; j < H; j += 256) {
        float v = xr[j];
        s += v; s2 += v * v;
    }
    float sum  = block_reduce_sum(s,  s0);
    float sum2 = block_reduce_sum(s2, s1);
    float mean = sum * (1.f / H);
    float var  = sum2 * (1.f / H) - mean * mean;
    float inv  = rsqrtf(var + 1e-6f);
    float* yr = y + (size_t)row * H;
    for (int j = threadIdx.x; j < H; j += 256)
        yr[j] = (xr[j] - mean) * inv * (1.f + sc[j]) + sh[j];
}

// ---------------- generic SGEMM NN: C = A(MxK) @ B(KxN) with epilogues ----------------
// mode 0: C = AB (+bias)
// mode 1: C = gelu_tanh(AB + bias)
// mode 2: C = residual + gate[col] * (AB + bias)
__global__ void __launch_bounds__(256) sgemm_nn(const float* __restrict__ A,
                                                const float* __restrict__ B,
                                                float* __restrict__ C,
                                                int M, int N, int K, int ldc,
                                                long long sA, long long sB, long long sC,
                                                const float* __restrict__ bias,
                                                const float* __restrict__ gate,
                                                const float* __restrict__ residual,
                                                int ldr, int mode) {
    A += (long long)blockIdx.z * sA;
    B += (long long)blockIdx.z * sB;
    C += (long long)blockIdx.z * sC;
    __shared__ float As[8][128];
    __shared__ float Bs[8][128];
    int tid = threadIdx.x;
    int bm = blockIdx.y * 128, bn = blockIdx.x * 128;
    int arow = tid >> 1,  acol = (tid & 1) * 4;
    int brow = tid >> 5,  bcol = (tid & 31) * 4;
    int ty = tid >> 4, tx = tid & 15;
    const float* Aptr = A + (long long)(bm + arow) * K + acol;
    const float* Bptr = B + (long long)brow * N + bn + bcol;
    float acc[8][8] = {};
    for (int k0 = 0; k0 < K; k0 += 8) {
        float4 a4 = *reinterpret_cast<const float4*>(Aptr + k0);
        float4 b4 = *reinterpret_cast<const float4*>(Bptr + (long long)k0 * N);
        __syncthreads();
        As[acol + 0][arow] = a4.x; As[acol + 1][arow] = a4.y;
        As[acol + 2][arow] = a4.z; As[acol + 3][arow] = a4.w;
        *reinterpret_cast<float4*>(&Bs[brow][bcol]) = b4;
        __syncthreads();
        #pragma unroll
        for (int kk = 0; kk < 8; kk++) {
            float af[8], bf[8];
            *reinterpret_cast<float4*>(af)     = *reinterpret_cast<const float4*>(&As[kk][ty * 8]);
            *reinterpret_cast<float4*>(af + 4) = *reinterpret_cast<const float4*>(&As[kk][ty * 8 + 4]);
            *reinterpret_cast<float4*>(bf)     = *reinterpret_cast<const float4*>(&Bs[kk][tx * 8]);
            *reinterpret_cast<float4*>(bf + 4) = *reinterpret_cast<const float4*>(&Bs[kk][tx * 8 + 4]);
            #pragma unroll
            for (int i = 0; i < 8; i++)
                #pragma unroll
                for (int j = 0; j < 8; j++)
                    acc[i][j] += af[i] * bf[j];
        }
    }
    #pragma unroll
    for (int i = 0; i < 8; i++) {
        int row = bm + ty * 8 + i;
        #pragma unroll
        for (int j = 0; j < 8; j++) {
            int col = bn + tx * 8 + j;
            float v = acc[i][j];
            if (bias) v += bias[col];
            if (mode == 1) {
                float xx = v;
                v = 0.5f * xx * (1.f + tanhf(0.7978845608028654f * (xx + 0.044715f * xx * xx * xx)));
            } else if (mode == 2) {
                v = residual[(long long)row * ldr + col] + gate[col] * v;
            }
            C[(long long)row * ldc + col] = v;
        }
    }
}

// ---------------- SGEMM NT: C = scale * A(MxK) @ B(NxK)^T (attention scores) ----------------
__global__ void __launch_bounds__(256) sgemm_nt(const float* __restrict__ A,
                                                const float* __restrict__ B,
                                                float* __restrict__ C,
                                                int M, int N, int K, int ldc,
                                                long long sA, long long sB, long long sC,
                                                float scale) {
    A += (long long)blockIdx.z * sA;
    B += (long long)blockIdx.z * sB;
    C += (long long)blockIdx.z * sC;
    __shared__ float As[8][128];
    __shared__ float Bs[8][128];
    int tid = threadIdx.x;
    int bm = blockIdx.y * 128, bn = blockIdx.x * 128;
    int arow = tid >> 1, acol = (tid & 1) * 4;
    int ty = tid >> 4, tx = tid & 15;
    const float* Aptr = A + (long long)(bm + arow) * K + acol;
    const float* Bptr = B + (long long)(bn + arow) * K + acol;
    float acc[8][8] = {};
    for (int k0 = 0; k0 < K; k0 += 8) {
        float4 a4 = *reinterpret_cast<const float4*>(Aptr + k0);
        float4 b4 = *reinterpret_cast<const float4*>(Bptr + k0);
        __syncthreads();
        As[acol + 0][arow] = a4.x; As[acol + 1][arow] = a4.y;
        As[acol + 2][arow] = a4.z; As[acol + 3][arow] = a4.w;
        Bs[acol + 0][arow] = b4.x; Bs[acol + 1][arow] = b4.y;
        Bs[acol + 2][arow] = b4.z; Bs[acol + 3][arow] = b4.w;
        __syncthreads();
        #pragma unroll
        for (int kk = 0; kk < 8; kk++) {
            float af[8], bf[8];
            *reinterpret_cast<float4*>(af)     = *reinterpret_cast<const float4*>(&As[kk][ty * 8]);
            *reinterpret_cast<float4*>(af + 4) = *reinterpret_cast<const float4*>(&As[kk][ty * 8 + 4]);
            *reinterpret_cast<float4*>(bf)     = *reinterpret_cast<const float4*>(&Bs[kk][tx * 8]);
            *reinterpret_cast<float4*>(bf + 4) = *reinterpret_cast<const float4*>(&Bs[kk][tx * 8 + 4]);
            #pragma unroll
            for (int i = 0; i < 8; i++)
                #pragma unroll
                for (int j = 0; j < 8; j++)
                    acc[i][j] += af[i] * bf[j];
        }
    }
    #pragma unroll
    for (int i = 0; i < 8; i++) {
        int row = bm + ty * 8 + i;
        #pragma unroll
        for (int j = 0; j < 8; j++) {
            int col = bn + tx * 8 + j;
            C[(long long)row * ldc + col] = acc[i][j] * scale;
        }
    }
}

// ---------------- QKV postprocess: bias-included qkv -> rms -> rope -> head-major q,k,v ----------------
__global__ void __launch_bounds__(128) qkv_post_kernel(const float* __restrict__ qkv,
                                                       const float* __restrict__ pe,
                                                       const float* __restrict__ nq_i,
                                                       const float* __restrict__ nk_i,
                                                       const float* __restrict__ nq_t,
                                                       const float* __restrict__ nk_t,
                                                       float* __restrict__ gq,
                                                       float* __restrict__ gk,
                                                       float* __restrict__ gv) {
    int s = blockIdx.x, h = blockIdx.y, d = threadIdx.x;
    const float* base = qkv + (size_t)s * QKV3 + h * HD;
    float qv = base[d], kv = base[H + d], vv = base[2 * H + d];
    float sq = qv * qv, sk = kv * kv;
    #pragma unroll
    for (int o = 16; o; o >>= 1) {
        sq += __shfl_xor_sync(0xffffffffu, sq, o);
        sk += __shfl_xor_sync(0xffffffffu, sk, o);
    }
    __shared__ float r0[4], r1[4];
    int w = d >> 5;
    if ((d & 31) == 0) { r0[w] = sq; r1[w] = sk; }
    __syncthreads();
    sq = r0[0] + r0[1] + r0[2] + r0[3];
    sk = r1[0] + r1[1] + r1[2] + r1[3];
    bool is_txt = s < LT;
    float qn = qv * rsqrtf(sq * (1.f / HD) + 1e-6f) * (is_txt ? nq_t[d] : nq_i[d]);
    float kn = kv * rsqrtf(sk * (1.f / HD) + 1e-6f) * (is_txt ? nk_t[d] : nk_i[d]);
    float qp = __shfl_xor_sync(0xffffffffu, qn, 1);
    float kp = __shfl_xor_sync(0xffffffffu, kn, 1);
    const float4 f = *reinterpret_cast<const float4*>(pe + ((size_t)s * 64 + (d >> 1)) * 4);
    float qo = (d & 1) ? (f.z * qp + f.w * qn) : (f.x * qn + f.y * qp);
    float ko = (d & 1) ? (f.z * kp + f.w * kn) : (f.x * kn + f.y * kp);
    size_t idx = ((size_t)h * L + s) * HD + d;
    gq[idx] = qo;
    gk[idx] = ko;
    gv[idx] = vv;
}

// ---------------- softmax over rows of S (register-resident: 1536 = 256*6) ----------------
__global__ void __launch_bounds__(256) softmax_rows(float* __restrict__ S) {
    __shared__ float s0[32], s1[32];
    float* row = S + (size_t)blockIdx.x * L;
    int t = threadIdx.x;
    float v[6];
    #pragma unroll
    for (int i = 0; i < 6; i++) v[i] = row[t + i * 256];
    float m = v[0];
    #pragma unroll
    for (int i = 1; i < 6; i++) m = fmaxf(m, v[i]);
    m = block_reduce_max(m, s0);
    float sum = 0.f;
    #pragma unroll
    for (int i = 0; i < 6; i++) { v[i] = __expf(v[i] - m); sum += v[i]; }
    sum = block_reduce_sum(sum, s1);
    float inv = 1.f / sum;
    #pragma unroll
    for (int i = 0; i < 6; i++) row[t + i * 256] = v[i] * inv;
}

// ---------------- launch ----------------
extern "C" void kernel_launch(void* const* d_in, const int* in_sizes, int n_in,
                              void* d_out, int out_size) {
    const float* img      = (const float*)d_in[0];
    const float* txt      = (const float*)d_in[1];
    const float* vec      = (const float*)d_in[2];
    const float* pe       = (const float*)d_in[3];
    const float* mod_w    = (const float*)d_in[4];
    const float* mod_b    = (const float*)d_in[5];
    const float* qkv_w    = (const float*)d_in[6];
    const float* qkv_b    = (const float*)d_in[7];
    const float* norm_q_w = (const float*)d_in[8];
    const float* norm_k_w = (const float*)d_in[9];
    const float* out_w    = (const float*)d_in[10];
    const float* out_b    = (const float*)d_in[11];
    const float* fc1_w    = (const float*)d_in[12];
    const float* fc1_b    = (const float*)d_in[13];
    const float* fc2_w    = (const float*)d_in[14];
    const float* fc2_b    = (const float*)d_in[15];
    const float* mod_c_w  = (const float*)d_in[16];
    const float* mod_c_b  = (const float*)d_in[17];
    const float* qkv_c_w  = (const float*)d_in[18];
    const float* qkv_c_b  = (const float*)d_in[19];
    const float* norm_aq_w= (const float*)d_in[20];
    const float* norm_ak_w= (const float*)d_in[21];
    const float* out_c_w  = (const float*)d_in[22];
    const float* out_c_b  = (const float*)d_in[23];
    const float* fc1_c_w  = (const float*)d_in[24];
    const float* fc1_c_b  = (const float*)d_in[25];
    const float* fc2_c_w  = (const float*)d_in[26];
    const float* fc2_c_b  = (const float*)d_in[27];
    float* out = (float*)d_out;

    float *modi, *modt, *xmod, *qkvb, *qb, *kb, *vb, *Sb, *attnb, *res2, *hb, *fc1b;
    cudaGetSymbolAddress((void**)&modi,  g_mod_img);
    cudaGetSymbolAddress((void**)&modt,  g_mod_txt);
    cudaGetSymbolAddress((void**)&xmod,  g_xmod);
    cudaGetSymbolAddress((void**)&qkvb,  g_qkv);
    cudaGetSymbolAddress((void**)&qb,    g_q);
    cudaGetSymbolAddress((void**)&kb,    g_k);
    cudaGetSymbolAddress((void**)&vb,    g_v);
    cudaGetSymbolAddress((void**)&Sb,    g_S);
    cudaGetSymbolAddress((void**)&attnb, g_attn);
    cudaGetSymbolAddress((void**)&res2,  g_res2);
    cudaGetSymbolAddress((void**)&hb,    g_hbuf);
    cudaGetSymbolAddress((void**)&fc1b,  g_fc1);

    // 1) modulation vectors
    mod_gemv<<<MOD6 / 256, 256>>>(vec, mod_w,   mod_b,   modi);
    mod_gemv<<<MOD6 / 256, 256>>>(vec, mod_c_w, mod_c_b, modt);

    // 2) LN + modulate (stage 1); unified layout [txt; img]
    ln_mod_kernel<<<LT, 256>>>(txt, xmod,                 modt,     modt + H);
    ln_mod_kernel<<<LI, 256>>>(img, xmod + (size_t)LT * H, modi,     modi + H);

    // 3) qkv GEMMs
    {
        dim3 gt(QKV3 / 128, LT / 128);
        sgemm_nn<<<gt, 256>>>(xmod, qkv_c_w, qkvb, LT, QKV3, H, QKV3, 0, 0, 0,
                              qkv_c_b, nullptr, nullptr, 0, 0);
        dim3 gi(QKV3 / 128, LI / 128);
        sgemm_nn<<<gi, 256>>>(xmod + (size_t)LT * H, qkv_w, qkvb + (size_t)LT * QKV3,
                              LI, QKV3, H, QKV3, 0, 0, 0,
                              qkv_b, nullptr, nullptr, 0, 0);
    }

    // 4) rms + rope + head-major split
    {
        dim3 g(L, NH);
        qkv_post_kernel<<<g, 128>>>(qkvb, pe, norm_q_w, norm_k_w, norm_aq_w, norm_ak_w,
                                    qb, kb, vb);
    }

    // 5) S = scale * Q K^T (batched over heads)
    {
        dim3 g(L / 128, L / 128, NH);
        sgemm_nt<<<g, 256>>>(qb, kb, Sb, L, L, HD, L,
                             (long long)L * HD, (long long)L * HD, (long long)L * L,
                             0.08838834764831845f);
    }

    // 6) softmax
    softmax_rows<<<NH * L, 256>>>(Sb);

    // 7) O = P V, written directly into [L, H] with per-head column offset
    {
        dim3 g(1, L / 128, NH);
        sgemm_nn<<<g, 256>>>(Sb, vb, attnb, L, HD, L, H,
                             (long long)L * L, (long long)L * HD, (long long)HD,
                             nullptr, nullptr, nullptr, 0, 0);
    }

    // 8) out projection + gated residual
    {
        dim3 gt(H / 128, LT / 128);
        sgemm_nn<<<gt, 256>>>(attnb, out_c_w, res2, LT, H, H, H, 0, 0, 0,
                              out_c_b, modt + 2 * H, txt, H, 2);
        dim3 gi(H / 128, LI / 128);
        sgemm_nn<<<gi, 256>>>(attnb + (size_t)LT * H, out_w, res2 + (size_t)LT * H,
                              LI, H, H, H, 0, 0, 0,
                              out_b, modi + 2 * H, img, H, 2);
    }

    // 9) LN + modulate (stage 2)
    ln_mod_kernel<<<LT, 256>>>(res2,                  hb,                  modt + 3 * H, modt + 4 * H);
    ln_mod_kernel<<<LI, 256>>>(res2 + (size_t)LT * H, hb + (size_t)LT * H, modi + 3 * H, modi + 4 * H);

    // 10) fc1 + gelu
    {
        dim3 gt(MLPD / 128, LT / 128);
        sgemm_nn<<<gt, 256>>>(hb, fc1_c_w, fc1b, LT, MLPD, H, MLPD, 0, 0, 0,
                              fc1_c_b, nullptr, nullptr, 0, 1);
        dim3 gi(MLPD / 128, LI / 128);
        sgemm_nn<<<gi, 256>>>(hb + (size_t)LT * H, fc1_w, fc1b + (size_t)LT * MLPD,
                              LI, MLPD, H, MLPD, 0, 0, 0,
                              fc1_b, nullptr, nullptr, 0, 1);
    }

    // 11) fc2 + gated residual -> final output (img first, then txt)
    {
        dim3 gt(H / 128, LT / 128);
        sgemm_nn<<<gt, 256>>>(fc1b, fc2_c_w, out + (size_t)LI * H, LT, H, MLPD, H, 0, 0, 0,
                              fc2_c_b, modt + 5 * H, res2, H, 2);
        dim3 gi(H / 128, LI / 128);
        sgemm_nn<<<gi, 256>>>(fc1b + (size_t)LT * MLPD, fc2_w, out, LI, H, MLPD, H, 0, 0, 0,
                              fc2_b, modi + 5 * H, res2 + (size_t)LT * H, H, 2);
    }
    (void)in_sizes; (void)n_in; (void)out_size;
}

// round 2
// speedup vs baseline: 2.7352x; 2.7352x over previous
#include <cuda_runtime.h>
#include <math.h>

#define H    3072
#define NH   24
#define HD   128
#define MLPD 12288
#define LT   512
#define LI   1024
#define L    1536
#define QKV3 9216
#define MOD6 18432

// ---------------- scratch (device globals; no allocations) ----------------
__device__ float g_mod_img[MOD6];
__device__ float g_mod_txt[MOD6];
__device__ float g_xmod[(size_t)L * H];
__device__ float g_qkv [(size_t)L * QKV3];
__device__ float g_q   [(size_t)NH * L * HD];
__device__ float g_k   [(size_t)NH * L * HD];
__device__ float g_v   [(size_t)NH * L * HD];
__device__ float g_S   [(size_t)NH * L * L];
__device__ float g_attn[(size_t)L * H];
__device__ float g_res2[(size_t)L * H];
__device__ float g_hbuf[(size_t)L * H];
__device__ float g_fc1 [(size_t)L * MLPD];

// ---------------- helpers ----------------
__device__ __forceinline__ float block_reduce_sum(float v, float* sh) {
    #pragma unroll
    for (int o = 16; o; o >>= 1) v += __shfl_xor_sync(0xffffffffu, v, o);
    int w = threadIdx.x >> 5;
    if ((threadIdx.x & 31) == 0) sh[w] = v;
    __syncthreads();
    if (threadIdx.x < 32) {
        float x = (threadIdx.x < (blockDim.x >> 5)) ? sh[threadIdx.x] : 0.f;
        #pragma unroll
        for (int o = 16; o; o >>= 1) x += __shfl_xor_sync(0xffffffffu, x, o);
        if (threadIdx.x == 0) sh[0] = x;
    }
    __syncthreads();
    return sh[0];
}

__device__ __forceinline__ float block_reduce_max(float v, float* sh) {
    #pragma unroll
    for (int o = 16; o; o >>= 1) v = fmaxf(v, __shfl_xor_sync(0xffffffffu, v, o));
    int w = threadIdx.x >> 5;
    if ((threadIdx.x & 31) == 0) sh[w] = v;
    __syncthreads();
    if (threadIdx.x < 32) {
        float x = (threadIdx.x < (blockDim.x >> 5)) ? sh[threadIdx.x] : -3.4e38f;
        #pragma unroll
        for (int o = 16; o; o >>= 1) x = fmaxf(x, __shfl_xor_sync(0xffffffffu, x, o));
        if (threadIdx.x == 0) sh[0] = x;
    }
    __syncthreads();
    return sh[0];
}

__device__ __forceinline__ unsigned f2tf(float x) {
    unsigned u;
    asm("cvt.rna.tf32.f32 %0, %1;" : "=r"(u) : "f"(x));
    return u;
}

__device__ __forceinline__ void mma_tf32(float* c, const unsigned* a, const unsigned* b) {
    asm volatile(
        "mma.sync.aligned.m16n8k8.row.col.f32.tf32.tf32.f32 "
        "{%0,%1,%2,%3}, {%4,%5,%6,%7}, {%8,%9}, {%0,%1,%2,%3};\n"
        : "+f"(c[0]), "+f"(c[1]), "+f"(c[2]), "+f"(c[3])
        : "r"(a[0]), "r"(a[1]), "r"(a[2]), "r"(a[3]), "r"(b[0]), "r"(b[1]));
}

__device__ __forceinline__ float gelu_tanh(float x) {
    return 0.5f * x * (1.f + tanhf(0.7978845608028654f * (x + 0.044715f * x * x * x)));
}

__device__ __forceinline__ uint4 cvt4(float4 v) {
    uint4 u;
    u.x = f2tf(v.x); u.y = f2tf(v.y); u.z = f2tf(v.z); u.w = f2tf(v.w);
    return u;
}

// ---------------- 1) modulation GEMV ----------------
__global__ void __launch_bounds__(256) mod_gemv(const float* __restrict__ vec,
                                                const float* __restrict__ w,
                                                const float* __restrict__ b,
                                                float* __restrict__ out) {
    __shared__ float sv[H];
    for (int i = threadIdx.x; i < H; i += 256) {
        float x = vec[i];
        sv[i] = x / (1.f + expf(-x));
    }
    __syncthreads();
    int col = blockIdx.x * 256 + threadIdx.x;
    float acc = b[col];
    const float* wp = w + col;
    #pragma unroll 8
    for (int i = 0; i < H; i++) acc += sv[i] * wp[(size_t)i * MOD6];
    out[col] = acc;
}

// ---------------- 2) LayerNorm + modulate ----------------
__global__ void __launch_bounds__(256) ln_mod_kernel(const float* __restrict__ x,
                                                     float* __restrict__ y,
                                                     const float* __restrict__ sh,
                                                     const float* __restrict__ sc) {
    __shared__ float s0[32], s1[32];
    int row = blockIdx.x;
    const float* xr = x + (size_t)row * H;
    float s = 0.f, s2 = 0.f;
    for (int j = threadIdx.x; j < H; j += 256) {
        float v = xr[j];
        s += v; s2 += v * v;
    }
    float sum  = block_reduce_sum(s,  s0);
    float sum2 = block_reduce_sum(s2, s1);
    float mean = sum * (1.f / H);
    float var  = sum2 * (1.f / H) - mean * mean;
    float inv  = rsqrtf(var + 1e-6f);
    float* yr = y + (size_t)row * H;
    for (int j = threadIdx.x; j < H; j += 256)
        yr[j] = (xr[j] - mean) * inv * (1.f + sc[j]) + sh[j];
}

// ---------------- TF32 tensor-core GEMM NN: C = A(MxK) @ B(KxN) ----------------
// mode 0: C = AB (+bias)
// mode 1: C = gelu_tanh(AB + bias)
// mode 2: C = residual + gate[col] * (AB + bias)
__global__ void __launch_bounds__(256, 2) tgemm_nn(const float* __restrict__ A,
                                                   const float* __restrict__ B,
                                                   float* __restrict__ C,
                                                   int N, int K, int ldc,
                                                   long long sA, long long sB, long long sC,
                                                   const float* __restrict__ bias,
                                                   const float* __restrict__ gate,
                                                   const float* __restrict__ residual,
                                                   int ldr, int mode) {
    A += (long long)blockIdx.z * sA;
    B += (long long)blockIdx.z * sB;
    C += (long long)blockIdx.z * sC;

    __shared__ unsigned As[2][128][20];   // [m][k], stride 20 -> conflict-free frag loads
    __shared__ unsigned Bs[2][16][136];   // [k][n], stride 136 -> tg*8 bank bases

    const int tid  = threadIdx.x;
    const int bm   = blockIdx.y * 128, bn = blockIdx.x * 128;
    const int lane = tid & 31, warp = tid >> 5;
    const int g = lane >> 2, tg = lane & 3;
    const int wm = (warp & 1) * 64, wn = (warp >> 1) * 32;

    const int arow = tid >> 2, acol = (tid & 3) * 4;
    const int brow = tid >> 5, bcol = (tid & 31) * 4;
    const float* Ap0 = A + (long long)(bm + arow) * K + acol;
    const float* Ap1 = Ap0 + (long long)64 * K;
    const float* Bp0 = B + (long long)brow * N + bn + bcol;
    const float* Bp1 = Bp0 + (long long)8 * N;

    float4 ra0 = *(const float4*)Ap0;
    float4 ra1 = *(const float4*)Ap1;
    float4 rb0 = *(const float4*)Bp0;
    float4 rb1 = *(const float4*)Bp1;

    *(uint4*)&As[0][arow][acol]      = cvt4(ra0);
    *(uint4*)&As[0][arow + 64][acol] = cvt4(ra1);
    *(uint4*)&Bs[0][brow][bcol]      = cvt4(rb0);
    *(uint4*)&Bs[0][brow + 8][bcol]  = cvt4(rb1);
    __syncthreads();

    float acc[4][4][4] = {};
    const int nk = K >> 4;
    for (int kb = 0; kb < nk; kb++) {
        const int p = kb & 1;
        if (kb + 1 < nk) {
            long long ko = (long long)(kb + 1) * 16;
            ra0 = *(const float4*)(Ap0 + ko);
            ra1 = *(const float4*)(Ap1 + ko);
            rb0 = *(const float4*)(Bp0 + ko * N);
            rb1 = *(const float4*)(Bp1 + ko * N);
        }
        #pragma unroll
        for (int ks = 0; ks < 16; ks += 8) {
            unsigned af[4][4];
            #pragma unroll
            for (int i = 0; i < 4; i++) {
                const unsigned* ap = &As[p][wm + i * 16 + g][ks + tg];
                af[i][0] = ap[0];
                af[i][1] = ap[8 * 20];
                af[i][2] = ap[4];
                af[i][3] = ap[8 * 20 + 4];
            }
            unsigned bf[4][2];
            #pragma unroll
            for (int j = 0; j < 4; j++) {
                bf[j][0] = Bs[p][ks + tg][wn + j * 8 + g];
                bf[j][1] = Bs[p][ks + tg + 4][wn + j * 8 + g];
            }
            #pragma unroll
            for (int i = 0; i < 4; i++)
                #pragma unroll
                for (int j = 0; j < 4; j++)
                    mma_tf32(acc[i][j], af[i], bf[j]);
        }
        if (kb + 1 < nk) {
            const int q = (kb + 1) & 1;
            *(uint4*)&As[q][arow][acol]      = cvt4(ra0);
            *(uint4*)&As[q][arow + 64][acol] = cvt4(ra1);
            *(uint4*)&Bs[q][brow][bcol]      = cvt4(rb0);
            *(uint4*)&Bs[q][brow + 8][bcol]  = cvt4(rb1);
        }
        __syncthreads();
    }

    #pragma unroll
    for (int i = 0; i < 4; i++) {
        int r0 = bm + wm + i * 16 + g;
        #pragma unroll
        for (int j = 0; j < 4; j++) {
            int c = bn + wn + j * 8 + 2 * tg;
            float v0 = acc[i][j][0], v1 = acc[i][j][1];
            float v2 = acc[i][j][2], v3 = acc[i][j][3];
            if (bias) {
                float b0 = bias[c], b1 = bias[c + 1];
                v0 += b0; v1 += b1; v2 += b0; v3 += b1;
            }
            if (mode == 1) {
                v0 = gelu_tanh(v0); v1 = gelu_tanh(v1);
                v2 = gelu_tanh(v2); v3 = gelu_tanh(v3);
            } else if (mode == 2) {
                const float* rr0 = residual + (long long)r0 * ldr + c;
                const float* rr1 = residual + (long long)(r0 + 8) * ldr + c;
                float g0 = gate[c], g1 = gate[c + 1];
                v0 = rr0[0] + g0 * v0; v1 = rr0[1] + g1 * v1;
                v2 = rr1[0] + g0 * v2; v3 = rr1[1] + g1 * v3;
            }
            float2 o0 = {v0, v1}, o1 = {v2, v3};
            *(float2*)&C[(long long)r0 * ldc + c]       = o0;
            *(float2*)&C[(long long)(r0 + 8) * ldc + c] = o1;
        }
    }
}

// ---------------- TF32 GEMM NT: C = scale * A(MxK) @ B(NxK)^T ----------------
__global__ void __launch_bounds__(256, 2) tgemm_nt(const float* __restrict__ A,
                                                   const float* __restrict__ B,
                                                   float* __restrict__ C,
                                                   int K, int ldc,
                                                   long long sA, long long sB, long long sC,
                                                   float scale) {
    A += (long long)blockIdx.z * sA;
    B += (long long)blockIdx.z * sB;
    C += (long long)blockIdx.z * sC;

    __shared__ unsigned As[2][128][20];
    __shared__ unsigned Bsn[2][128][20];  // [n][k]

    const int tid  = threadIdx.x;
    const int bm   = blockIdx.y * 128, bn = blockIdx.x * 128;
    const int lane = tid & 31, warp = tid >> 5;
    const int g = lane >> 2, tg = lane & 3;
    const int wm = (warp & 1) * 64, wn = (warp >> 1) * 32;

    const int arow = tid >> 2, acol = (tid & 3) * 4;
    const float* Ap0 = A + (long long)(bm + arow) * K + acol;
    const float* Ap1 = Ap0 + (long long)64 * K;
    const float* Bp0 = B + (long long)(bn + arow) * K + acol;
    const float* Bp1 = Bp0 + (long long)64 * K;

    float4 ra0 = *(const float4*)Ap0;
    float4 ra1 = *(const float4*)Ap1;
    float4 rb0 = *(const float4*)Bp0;
    float4 rb1 = *(const float4*)Bp1;

    *(uint4*)&As[0][arow][acol]       = cvt4(ra0);
    *(uint4*)&As[0][arow + 64][acol]  = cvt4(ra1);
    *(uint4*)&Bsn[0][arow][acol]      = cvt4(rb0);
    *(uint4*)&Bsn[0][arow + 64][acol] = cvt4(rb1);
    __syncthreads();

    float acc[4][4][4] = {};
    const int nk = K >> 4;
    for (int kb = 0; kb < nk; kb++) {
        const int p = kb & 1;
        if (kb + 1 < nk) {
            long long ko = (long long)(kb + 1) * 16;
            ra0 = *(const float4*)(Ap0 + ko);
            ra1 = *(const float4*)(Ap1 + ko);
            rb0 = *(const float4*)(Bp0 + ko);
            rb1 = *(const float4*)(Bp1 + ko);
        }
        #pragma unroll
        for (int ks = 0; ks < 16; ks += 8) {
            unsigned af[4][4];
            #pragma unroll
            for (int i = 0; i < 4; i++) {
                const unsigned* ap = &As[p][wm + i * 16 + g][ks + tg];
                af[i][0] = ap[0];
                af[i][1] = ap[8 * 20];
                af[i][2] = ap[4];
                af[i][3] = ap[8 * 20 + 4];
            }
            unsigned bf[4][2];
            #pragma unroll
            for (int j = 0; j < 4; j++) {
                const unsigned* bp = &Bsn[p][wn + j * 8 + g][ks + tg];
                bf[j][0] = bp[0];
                bf[j][1] = bp[4];
            }
            #pragma unroll
            for (int i = 0; i < 4; i++)
                #pragma unroll
                for (int j = 0; j < 4; j++)
                    mma_tf32(acc[i][j], af[i], bf[j]);
        }
        if (kb + 1 < nk) {
            const int q = (kb + 1) & 1;
            *(uint4*)&As[q][arow][acol]       = cvt4(ra0);
            *(uint4*)&As[q][arow + 64][acol]  = cvt4(ra1);
            *(uint4*)&Bsn[q][arow][acol]      = cvt4(rb0);
            *(uint4*)&Bsn[q][arow + 64][acol] = cvt4(rb1);
        }
        __syncthreads();
    }

    #pragma unroll
    for (int i = 0; i < 4; i++) {
        int r0 = bm + wm + i * 16 + g;
        #pragma unroll
        for (int j = 0; j < 4; j++) {
            int c = bn + wn + j * 8 + 2 * tg;
            float2 o0 = {acc[i][j][0] * scale, acc[i][j][1] * scale};
            float2 o1 = {acc[i][j][2] * scale, acc[i][j][3] * scale};
            *(float2*)&C[(long long)r0 * ldc + c]       = o0;
            *(float2*)&C[(long long)(r0 + 8) * ldc + c] = o1;
        }
    }
}

// ---------------- QKV postprocess ----------------
__global__ void __launch_bounds__(128) qkv_post_kernel(const float* __restrict__ qkv,
                                                       const float* __restrict__ pe,
                                                       const float* __restrict__ nq_i,
                                                       const float* __restrict__ nk_i,
                                                       const float* __restrict__ nq_t,
                                                       const float* __restrict__ nk_t,
                                                       float* __restrict__ gq,
                                                       float* __restrict__ gk,
                                                       float* __restrict__ gv) {
    int s = blockIdx.x, h = blockIdx.y, d = threadIdx.x;
    const float* base = qkv + (size_t)s * QKV3 + h * HD;
    float qv = base[d], kv = base[H + d], vv = base[2 * H + d];
    float sq = qv * qv, sk = kv * kv;
    #pragma unroll
    for (int o = 16; o; o >>= 1) {
        sq += __shfl_xor_sync(0xffffffffu, sq, o);
        sk += __shfl_xor_sync(0xffffffffu, sk, o);
    }
    __shared__ float r0[4], r1[4];
    int w = d >> 5;
    if ((d & 31) == 0) { r0[w] = sq; r1[w] = sk; }
    __syncthreads();
    sq = r0[0] + r0[1] + r0[2] + r0[3];
    sk = r1[0] + r1[1] + r1[2] + r1[3];
    bool is_txt = s < LT;
    float qn = qv * rsqrtf(sq * (1.f / HD) + 1e-6f) * (is_txt ? nq_t[d] : nq_i[d]);
    float kn = kv * rsqrtf(sk * (1.f / HD) + 1e-6f) * (is_txt ? nk_t[d] : nk_i[d]);
    float qp = __shfl_xor_sync(0xffffffffu, qn, 1);
    float kp = __shfl_xor_sync(0xffffffffu, kn, 1);
    const float4 f = *reinterpret_cast<const float4*>(pe + ((size_t)s * 64 + (d >> 1)) * 4);
    float qo = (d & 1) ? (f.z * qp + f.w * qn) : (f.x * qn + f.y * qp);
    float ko = (d & 1) ? (f.z * kp + f.w * kn) : (f.x * kn + f.y * kp);
    size_t idx = ((size_t)h * L + s) * HD + d;
    gq[idx] = qo;
    gk[idx] = ko;
    gv[idx] = vv;
}

// ---------------- softmax over rows of S ----------------
__global__ void __launch_bounds__(256) softmax_rows(float* __restrict__ S) {
    __shared__ float s0[32], s1[32];
    float* row = S + (size_t)blockIdx.x * L;
    int t = threadIdx.x;
    float v[6];
    #pragma unroll
    for (int i = 0; i < 6; i++) v[i] = row[t + i * 256];
    float m = v[0];
    #pragma unroll
    for (int i = 1; i < 6; i++) m = fmaxf(m, v[i]);
    m = block_reduce_max(m, s0);
    float sum = 0.f;
    #pragma unroll
    for (int i = 0; i < 6; i++) { v[i] = __expf(v[i] - m); sum += v[i]; }
    sum = block_reduce_sum(sum, s1);
    float inv = 1.f / sum;
    #pragma unroll
    for (int i = 0; i < 6; i++) row[t + i * 256] = v[i] * inv;
}

// ---------------- launch ----------------
extern "C" void kernel_launch(void* const* d_in, const int* in_sizes, int n_in,
                              void* d_out, int out_size) {
    const float* img      = (const float*)d_in[0];
    const float* txt      = (const float*)d_in[1];
    const float* vec      = (const float*)d_in[2];
    const float* pe       = (const float*)d_in[3];
    const float* mod_w    = (const float*)d_in[4];
    const float* mod_b    = (const float*)d_in[5];
    const float* qkv_w    = (const float*)d_in[6];
    const float* qkv_b    = (const float*)d_in[7];
    const float* norm_q_w = (const float*)d_in[8];
    const float* norm_k_w = (const float*)d_in[9];
    const float* out_w    = (const float*)d_in[10];
    const float* out_b    = (const float*)d_in[11];
    const float* fc1_w    = (const float*)d_in[12];
    const float* fc1_b    = (const float*)d_in[13];
    const float* fc2_w    = (const float*)d_in[14];
    const float* fc2_b    = (const float*)d_in[15];
    const float* mod_c_w  = (const float*)d_in[16];
    const float* mod_c_b  = (const float*)d_in[17];
    const float* qkv_c_w  = (const float*)d_in[18];
    const float* qkv_c_b  = (const float*)d_in[19];
    const float* norm_aq_w= (const float*)d_in[20];
    const float* norm_ak_w= (const float*)d_in[21];
    const float* out_c_w  = (const float*)d_in[22];
    const float* out_c_b  = (const float*)d_in[23];
    const float* fc1_c_w  = (const float*)d_in[24];
    const float* fc1_c_b  = (const float*)d_in[25];
    const float* fc2_c_w  = (const float*)d_in[26];
    const float* fc2_c_b  = (const float*)d_in[27];
    float* out = (float*)d_out;

    float *modi, *modt, *xmod, *qkvb, *qb, *kb, *vb, *Sb, *attnb, *res2, *hb, *fc1b;
    cudaGetSymbolAddress((void**)&modi,  g_mod_img);
    cudaGetSymbolAddress((void**)&modt,  g_mod_txt);
    cudaGetSymbolAddress((void**)&xmod,  g_xmod);
    cudaGetSymbolAddress((void**)&qkvb,  g_qkv);
    cudaGetSymbolAddress((void**)&qb,    g_q);
    cudaGetSymbolAddress((void**)&kb,    g_k);
    cudaGetSymbolAddress((void**)&vb,    g_v);
    cudaGetSymbolAddress((void**)&Sb,    g_S);
    cudaGetSymbolAddress((void**)&attnb, g_attn);
    cudaGetSymbolAddress((void**)&res2,  g_res2);
    cudaGetSymbolAddress((void**)&hb,    g_hbuf);
    cudaGetSymbolAddress((void**)&fc1b,  g_fc1);

    // 1) modulation vectors
    mod_gemv<<<MOD6 / 256, 256>>>(vec, mod_w,   mod_b,   modi);
    mod_gemv<<<MOD6 / 256, 256>>>(vec, mod_c_w, mod_c_b, modt);

    // 2) LN + modulate (stage 1); unified layout [txt; img]
    ln_mod_kernel<<<LT, 256>>>(txt, xmod,                  modt, modt + H);
    ln_mod_kernel<<<LI, 256>>>(img, xmod + (size_t)LT * H, modi, modi + H);

    // 3) qkv GEMMs (tf32)
    {
        dim3 gt(QKV3 / 128, LT / 128);
        tgemm_nn<<<gt, 256>>>(xmod, qkv_c_w, qkvb, QKV3, H, QKV3, 0, 0, 0,
                              qkv_c_b, nullptr, nullptr, 0, 0);
        dim3 gi(QKV3 / 128, LI / 128);
        tgemm_nn<<<gi, 256>>>(xmod + (size_t)LT * H, qkv_w, qkvb + (size_t)LT * QKV3,
                              QKV3, H, QKV3, 0, 0, 0,
                              qkv_b, nullptr, nullptr, 0, 0);
    }

    // 4) rms + rope + head-major split
    {
        dim3 g(L, NH);
        qkv_post_kernel<<<g, 128>>>(qkvb, pe, norm_q_w, norm_k_w, norm_aq_w, norm_ak_w,
                                    qb, kb, vb);
    }

    // 5) S = scale * Q K^T (batched over heads)
    {
        dim3 g(L / 128, L / 128, NH);
        tgemm_nt<<<g, 256>>>(qb, kb, Sb, HD, L,
                             (long long)L * HD, (long long)L * HD, (long long)L * L,
                             0.08838834764831845f);
    }

    // 6) softmax
    softmax_rows<<<NH * L, 256>>>(Sb);

    // 7) O = P V, written directly into [L, H] with per-head column offset
    {
        dim3 g(1, L / 128, NH);
        tgemm_nn<<<g, 256>>>(Sb, vb, attnb, HD, L, H,
                             (long long)L * L, (long long)L * HD, (long long)HD,
                             nullptr, nullptr, nullptr, 0, 0);
    }

    // 8) out projection + gated residual
    {
        dim3 gt(H / 128, LT / 128);
        tgemm_nn<<<gt, 256>>>(attnb, out_c_w, res2, H, H, H, 0, 0, 0,
                              out_c_b, modt + 2 * H, txt, H, 2);
        dim3 gi(H / 128, LI / 128);
        tgemm_nn<<<gi, 256>>>(attnb + (size_t)LT * H, out_w, res2 + (size_t)LT * H,
                              H, H, H, 0, 0, 0,
                              out_b, modi + 2 * H, img, H, 2);
    }

    // 9) LN + modulate (stage 2)
    ln_mod_kernel<<<LT, 256>>>(res2,                  hb,                  modt + 3 * H, modt + 4 * H);
    ln_mod_kernel<<<LI, 256>>>(res2 + (size_t)LT * H, hb + (size_t)LT * H, modi + 3 * H, modi + 4 * H);

    // 10) fc1 + gelu
    {
        dim3 gt(MLPD / 128, LT / 128);
        tgemm_nn<<<gt, 256>>>(hb, fc1_c_w, fc1b, MLPD, H, MLPD, 0, 0, 0,
                              fc1_c_b, nullptr, nullptr, 0, 1);
        dim3 gi(MLPD / 128, LI / 128);
        tgemm_nn<<<gi, 256>>>(hb + (size_t)LT * H, fc1_w, fc1b + (size_t)LT * MLPD,
                              MLPD, H, MLPD, 0, 0, 0,
                              fc1_b, nullptr, nullptr, 0, 1);
    }

    // 11) fc2 + gated residual -> final output (img first, then txt)
    {
        dim3 gt(H / 128, LT / 128);
        tgemm_nn<<<gt, 256>>>(fc1b, fc2_c_w, out + (size_t)LI * H, H, MLPD, H, 0, 0, 0,
                              fc2_c_b, modt + 5 * H, res2, H, 2);
        dim3 gi(H / 128, LI / 128);
        tgemm_nn<<<gi, 256>>>(fc1b + (size_t)LT * MLPD, fc2_w, out, H, MLPD, H, 0, 0, 0,
                              fc2_b, modi + 5 * H, res2 + (size_t)LT * H, H, 2);
    }
    (void)in_sizes; (void)n_in; (void)out_size;
}